// round 12
// baseline (speedup 1.0000x reference)
#include <cuda_runtime.h>
#include <cuda_bf16.h>

#define NQ 4
#define DIM 16
#define NGATES 16      // NUM_LAYERS * NQ
#define NUM_LAYERS 4
#define THREADS 256

__device__ float4 g_table[DIM];

// ===================== Builder: 1 block, shuffle-parallel =====================
__global__ void __launch_bounds__(THREADS)
vqc_build(const float* __restrict__ wa,   // (4,2,3)
          const float* __restrict__ wb,   // (4,2,3)
          const float* __restrict__ sa,   // (2,)
          const float* __restrict__ sb) { // (2,)
    __shared__ float U[NGATES][8];
    const int tid = threadIdx.x;

    if (tid < NGATES) {
        int l = tid >> 2, wire = tid & 3;
        const float* p = (wire < 2) ? (wa + l * 6 + wire * 3)
                                    : (wb + l * 6 + (wire - 2) * 3);
        float phi = p[0], theta = p[1], omega = p[2];
        float cc, s;    __sincosf(theta * 0.5f, &s, &cc);
        float sm, cm;   __sincosf(-0.5f * (phi + omega), &sm, &cm);
        float sp, cp;   __sincosf( 0.5f * (phi + omega), &sp, &cp);
        float sdm, cdm; __sincosf(-0.5f * (phi - omega), &sdm, &cdm);
        float sdp, cdp; __sincosf( 0.5f * (phi - omega), &sdp, &cdp);
        U[tid][0] = cm * cc;   U[tid][1] = sm * cc;
        U[tid][2] = -cdp * s;  U[tid][3] = -sdp * s;
        U[tid][4] = cdm * s;   U[tid][5] = sdm * s;
        U[tid][6] = cp * cc;   U[tid][7] = sp * cc;
    }
    __syncthreads();

    // 16 columns x 16 amplitudes: one complex amplitude per thread.
    const int lane = tid & 31;
    const int idx  = tid & 15;
    const int col  = tid >> 4;
    float re = (idx == col) ? 1.0f : 0.0f;
    float im = 0.0f;

    const int ctrl[4] = {0, 2, 0, 0};
    const int targ[4] = {1, 3, 2, 3};

#pragma unroll
    for (int l = 0; l < NUM_LAYERS; l++) {
#pragma unroll
        for (int wire = 0; wire < NQ; wire++) {
            const int g = l * 4 + wire;
            const int m = 1 << (NQ - 1 - wire);
            float pre = __shfl_xor_sync(0xFFFFFFFFu, re, m);
            float pim = __shfl_xor_sync(0xFFFFFFFFu, im, m);
            bool hi = (idx & m) != 0;
            float Xr = hi ? U[g][6] : U[g][0];
            float Xi = hi ? U[g][7] : U[g][1];
            float Yr = hi ? U[g][4] : U[g][2];
            float Yi = hi ? U[g][5] : U[g][3];
            float nre = Xr * re - Xi * im + Yr * pre - Yi * pim;
            float nim = Xr * im + Xi * re + Yr * pim + Yi * pre;
            re = nre; im = nim;
        }
#pragma unroll
        for (int gg = 0; gg < 4; gg++) {
            const int cb = NQ - 1 - ctrl[gg];
            const int tb = NQ - 1 - targ[gg];
            int src = idx ^ (((idx >> cb) & 1) << tb);
            int srcLane = (lane & 0x10) | src;
            re = __shfl_sync(0xFFFFFFFFu, re, srcLane);
            im = __shfl_sync(0xFFFFFFFFu, im, srcLane);
        }
    }

    float p = re * re + im * im;
    float z0 = ((idx >> 3) & 1) ? -p : p;
    float z1 = ((idx >> 2) & 1) ? -p : p;
    float z2 = ((idx >> 1) & 1) ? -p : p;
    float z3 = ( idx       & 1) ? -p : p;
#pragma unroll
    for (int off = 1; off < 16; off <<= 1) {
        z0 += __shfl_xor_sync(0xFFFFFFFFu, z0, off);
        z1 += __shfl_xor_sync(0xFFFFFFFFu, z1, off);
        z2 += __shfl_xor_sync(0xFFFFFFFFu, z2, off);
        z3 += __shfl_xor_sync(0xFFFFFFFFu, z3, off);
    }
    if (idx == 0) {
        float4 r;
        r.x = (z0 + 1.0f) * 0.5f * sa[0];
        r.y = (z1 + 1.0f) * 0.5f * sa[1];
        r.z = (z2 + 1.0f) * 0.5f * sb[0];
        r.w = (z3 + 1.0f) * 0.5f * sb[1];
        g_table[col] = r;
    }
    __syncthreads();
    __threadfence();
    // Release dependent grid: writes before this trigger are visible to the
    // dependent after its griddepcontrol.wait.
    asm volatile("griddepcontrol.launch_dependents;" ::: "memory");
}

// ===================== Gather: PDL-dependent kernel =====================
__global__ void __launch_bounds__(THREADS)
vqc_gather(const int2* __restrict__ x1,
           const int2* __restrict__ x2,
           float4* __restrict__ out,
           int n) {
    const int gid = blockIdx.x * THREADS + threadIdx.x;

    // Independent input loads first: their latency overlaps the builder's tail
    // (this kernel's blocks start while the builder is still running).
    int2 a, c;
    bool v = (gid < n);
    if (v) { a = x1[gid]; c = x2[gid]; }

    // HW wait for the builder (no L2 flag polling, no block barrier).
    asm volatile("griddepcontrol.wait;" ::: "memory");

    if (v) {
        out[gid] = g_table[(a.x << 3) | (a.y << 2) | (c.x << 1) | c.y];
    }
}

extern "C" void kernel_launch(void* const* d_in, const int* in_sizes, int n_in,
                              void* d_out, int out_size) {
    const int2*  x1 = (const int2*) d_in[0];
    const int2*  x2 = (const int2*) d_in[1];
    const float* wa = (const float*)d_in[2];
    const float* wb = (const float*)d_in[3];
    const float* sa = (const float*)d_in[4];
    const float* sb = (const float*)d_in[5];
    float4* out = (float4*)d_out;

    int batch = in_sizes[0] / 2;   // x1 is (BATCH, 2) int32
    int blocks = (batch + THREADS - 1) / THREADS;
    if (blocks < 1) blocks = 1;

    vqc_build<<<1, THREADS>>>(wa, wb, sa, sb);

    // Launch gather as a programmatic-dependent kernel: it may begin executing
    // while the builder runs; griddepcontrol.wait enforces correctness.
    cudaLaunchConfig_t cfg = {};
    cfg.gridDim  = dim3((unsigned)blocks, 1, 1);
    cfg.blockDim = dim3(THREADS, 1, 1);
    cfg.dynamicSmemBytes = 0;
    cfg.stream = 0;
    cudaLaunchAttribute attrs[1];
    attrs[0].id = cudaLaunchAttributeProgrammaticStreamSerialization;
    attrs[0].val.programmaticStreamSerializationAllowed = 1;
    cfg.attrs = attrs;
    cfg.numAttrs = 1;

    cudaError_t err = cudaLaunchKernelEx(&cfg, vqc_gather, x1, x2, out, batch);
    if (err != cudaSuccess) {
        // Fallback: plain launch — stream ordering alone guarantees correctness
        // (griddepcontrol.wait is a no-op when no PDL is configured).
        vqc_gather<<<blocks, THREADS>>>(x1, x2, out, batch);
    }
}